// round 4
// baseline (speedup 1.0000x reference)
#include <cuda_runtime.h>

#define NNODE 8000
#define TDIM 12
#define FDIM 5
#define RBLOCKS 63   // 63 * 128 = 8064 >= 8000

// Scratch (device globals; no allocation allowed)
__device__ float g_partial[RBLOCKS][128]; // [b][0:64)=lhs1 comps (t*5+f, 60 valid)
                                          // [b][64:128)=M comps (f*12+t', 60 valid)
__device__ float g_At2[144];              // At2[t'][t], row-major 12x12
__device__ unsigned int g_ticket;         // zero-init; self-resetting each launch

// ---------------------------------------------------------------------------
// Halving butterfly: reduce 64 values across 32 lanes with 62 shuffles.
// On exit lane l holds component sums at indices v[0],v[1] = comps 2l, 2l+1.
// ---------------------------------------------------------------------------
__device__ __forceinline__ void butterfly64(float* v, int lane) {
#pragma unroll
    for (int s = 0; s < 5; s++) {
        const int mask = 16 >> s;
        const int half = 32 >> s;
        const bool up = (lane & mask) != 0;
#pragma unroll
        for (int j = 0; j < half; j++) {
            float send = up ? v[j] : v[half + j];
            float recv = __shfl_xor_sync(0xffffffffu, send, mask);
            v[j] = (up ? v[half + j] : v[j]) + recv;
        }
    }
}

// ---------------------------------------------------------------------------
// K1: partial reductions over n; last block finishes and computes At2.
//   lhs1[t,f] = sum_n U1[n] * x[n,t,f]
//   M[f,t']   = sum_n U2[f,n] * (sum_g U3[g]*x[n,t',g])
//   At2 = softmax_col( Ve @ sigmoid(lhs1 @ M + be) )
// ---------------------------------------------------------------------------
__global__ void __launch_bounds__(128) k_reduce_att(
    const float* __restrict__ x, const float* __restrict__ U1,
    const float* __restrict__ U2, const float* __restrict__ U3,
    const float* __restrict__ be, const float* __restrict__ Ve)
{
    const int tid = threadIdx.x;
    const int lane = tid & 31;
    const int warp = tid >> 5;
    const int n = blockIdx.x * 128 + tid;

    float xr[60];
    float u1 = 0.f, u2[5];
#pragma unroll
    for (int f = 0; f < 5; f++) u2[f] = 0.f;
    if (n < NNODE) {
        const float4* xp = (const float4*)(x + (size_t)n * 60);
#pragma unroll
        for (int i = 0; i < 15; i++) {
            float4 q = xp[i];
            xr[4 * i + 0] = q.x; xr[4 * i + 1] = q.y;
            xr[4 * i + 2] = q.z; xr[4 * i + 3] = q.w;
        }
        u1 = U1[n];
#pragma unroll
        for (int f = 0; f < 5; f++) u2[f] = U2[f * NNODE + n];
    } else {
#pragma unroll
        for (int j = 0; j < 60; j++) xr[j] = 0.f;
    }

    float u3[5];
#pragma unroll
    for (int f = 0; f < 5; f++) u3[f] = U3[f];

    // rhs[t'] = sum_g U3[g] * x[n,t',g]
    float rhs[12];
#pragma unroll
    for (int t = 0; t < 12; t++) {
        float s = 0.f;
#pragma unroll
        for (int f = 0; f < 5; f++) s += u3[f] * xr[t * 5 + f];
        rhs[t] = s;
    }

    __shared__ float sA[4][64], sB[4][64];

    // --- lhs1 contributions: v[j] = u1 * x[n,j], j = t*5+f ---
    {
        float v[64];
#pragma unroll
        for (int j = 0; j < 60; j++) v[j] = u1 * xr[j];
#pragma unroll
        for (int j = 60; j < 64; j++) v[j] = 0.f;
        butterfly64(v, lane);
        sA[warp][2 * lane + 0] = v[0];
        sA[warp][2 * lane + 1] = v[1];
    }
    // --- M contributions: v[f*12+t'] = u2[f] * rhs[t'] ---
    {
        float v[64];
#pragma unroll
        for (int f = 0; f < 5; f++)
#pragma unroll
            for (int t = 0; t < 12; t++) v[f * 12 + t] = u2[f] * rhs[t];
#pragma unroll
        for (int j = 60; j < 64; j++) v[j] = 0.f;
        butterfly64(v, lane);
        sB[warp][2 * lane + 0] = v[0];
        sB[warp][2 * lane + 1] = v[1];
    }
    __syncthreads();

    // cross-warp: 128 threads, first 64 -> lhs comps, next 64 -> M comps
    {
        float s = 0.f;
        if (tid < 64) {
#pragma unroll
            for (int w = 0; w < 4; w++) s += sA[w][tid];
        } else {
#pragma unroll
            for (int w = 0; w < 4; w++) s += sB[w][tid - 64];
        }
        g_partial[blockIdx.x][tid] = s;
    }

    // --- last block finishes reduction + attention ---
    __threadfence();
    __shared__ unsigned int s_ticket;
    if (tid == 0) s_ticket = atomicAdd(&g_ticket, 1u);
    __syncthreads();
    if (s_ticket != (unsigned)(gridDim.x - 1)) return;

    __shared__ float lhs[64], M[64], S[144], E[144];
    {
        float s = 0.f;
#pragma unroll 1
        for (int b = 0; b < RBLOCKS; b++) s += g_partial[b][tid];
        if (tid < 64) lhs[tid] = s;
        else          M[tid - 64] = s;
    }
    __syncthreads();
    for (int j = tid; j < 144; j += 128) {
        int i = j / 12, c = j % 12;
        float p = 0.f;
#pragma unroll
        for (int f = 0; f < 5; f++) p += lhs[i * 5 + f] * M[f * 12 + c];
        p += be[j];
        S[j] = 1.f / (1.f + expf(-p));
    }
    __syncthreads();
    for (int j = tid; j < 144; j += 128) {
        int i = j / 12, c = j % 12;
        float e = 0.f;
#pragma unroll
        for (int k = 0; k < 12; k++) e += Ve[i * 12 + k] * S[k * 12 + c];
        E[j] = e;
    }
    __syncthreads();
    for (int j = tid; j < 144; j += 128) {
        int c = j % 12;
        float mx = -1e30f;
#pragma unroll
        for (int k = 0; k < 12; k++) mx = fmaxf(mx, E[k * 12 + c]);
        float sum = 0.f;
#pragma unroll
        for (int k = 0; k < 12; k++) sum += expf(E[k * 12 + c] - mx);
        g_At2[j] = expf(E[j] - mx) / sum;
    }
    if (tid == 0) g_ticket = 0u;  // reset for next graph replay
}

// ---------------------------------------------------------------------------
// K2: per node n, split over 2 threads by t-halves:
//   x2[f][t] = sum_{t'} x[n,t',f] * At2[t'][t]   (halo of 1 t each side)
//   y[o][t]  = b2[o] + sum_i sum_k w2[o,i,k]*x2[i][t+k-1]
// Output in (o, n, t) row-major == flat output buffer.
// ---------------------------------------------------------------------------
template <int H>
__device__ __forceinline__ void node_half(
    const float* __restrict__ xr, const float* __restrict__ sA,
    const float* __restrict__ sw, const float* __restrict__ sb,
    int n, float* __restrict__ out)
{
    const int tlo = H ? 5 : 0;   // x2 covers t = tlo .. tlo+6
    float x2[5][7];
#pragma unroll
    for (int f = 0; f < 5; f++)
#pragma unroll
        for (int k = 0; k < 7; k++) x2[f][k] = 0.f;

#pragma unroll
    for (int tp = 0; tp < 12; tp++) {
        float a[7];
#pragma unroll
        for (int k = 0; k < 7; k++) a[k] = sA[tp * 12 + tlo + k];
#pragma unroll
        for (int f = 0; f < 5; f++) {
            float xv = xr[tp * 5 + f];
#pragma unroll
            for (int k = 0; k < 7; k++) x2[f][k] += xv * a[k];
        }
    }

#pragma unroll
    for (int o = 0; o < 5; o++) {
        float wr[15];
#pragma unroll
        for (int q = 0; q < 15; q++) wr[q] = sw[o * 15 + q];
        float y[6];
#pragma unroll
        for (int u = 0; u < 6; u++) {
            const int t = 6 * H + u;
            const int k = t - tlo;
            float acc = sb[o];
#pragma unroll
            for (int i = 0; i < 5; i++) {
                if (t > 0)  acc += wr[i * 3 + 0] * x2[i][k - 1];
                acc += wr[i * 3 + 1] * x2[i][k];
                if (t < 11) acc += wr[i * 3 + 2] * x2[i][k + 1];
            }
            y[u] = acc;
        }
        float2* op = (float2*)(out + (size_t)o * NNODE * TDIM
                                   + (size_t)n * TDIM + 6 * H);
        op[0] = make_float2(y[0], y[1]);
        op[1] = make_float2(y[2], y[3]);
        op[2] = make_float2(y[4], y[5]);
    }
}

__global__ void __launch_bounds__(256) k_main(
    const float* __restrict__ x, const float* __restrict__ w2,
    const float* __restrict__ b2, float* __restrict__ out)
{
    __shared__ float sA[144], sw[75], sb[5];
    const int tid = threadIdx.x;
    for (int j = tid; j < 144; j += 256) sA[j] = g_At2[j];
    if (tid < 75) sw[tid] = w2[tid];
    if (tid < 5)  sb[tid] = b2[tid];
    __syncthreads();

    const int idx = blockIdx.x * 256 + tid;
    const int n = idx >> 1;
    const int h = idx & 1;
    if (n >= NNODE) return;

    float xr[60];
    const float4* xp = (const float4*)(x + (size_t)n * 60);
#pragma unroll
    for (int i = 0; i < 15; i++) {
        float4 q = xp[i];
        xr[4 * i + 0] = q.x; xr[4 * i + 1] = q.y;
        xr[4 * i + 2] = q.z; xr[4 * i + 3] = q.w;
    }

    if (h == 0) node_half<0>(xr, sA, sw, sb, n, out);
    else        node_half<1>(xr, sA, sw, sb, n, out);
}

extern "C" void kernel_launch(void* const* d_in, const int* in_sizes, int n_in,
                              void* d_out, int out_size)
{
    // metadata order: x, adj, U1_1, U2_1, U3_1, be_1, Ve_1,
    //                 U1_2, U2_2, U3_2, be_2, Ve_2,
    //                 conv1_w, conv1_b, conv2_w, conv2_b, W_hgc, b_hgc
    const float* x  = (const float*)d_in[0];
    const float* U1 = (const float*)d_in[7];
    const float* U2 = (const float*)d_in[8];
    const float* U3 = (const float*)d_in[9];
    const float* be = (const float*)d_in[10];
    const float* Ve = (const float*)d_in[11];
    const float* w2 = (const float*)d_in[14];
    const float* b2 = (const float*)d_in[15];
    float* out = (float*)d_out;

    k_reduce_att<<<RBLOCKS, 128>>>(x, U1, U2, U3, be, Ve);
    k_main<<<(2 * NNODE + 255) / 256, 256>>>(x, w2, b2, out);
}

// round 5
// speedup vs baseline: 1.1001x; 1.1001x over previous
#include <cuda_runtime.h>

#define NNODE 8000
#define TDIM 12
#define NBLK 125
#define NPB 64      // nodes per block (125*64 = 8000)
#define XROW 61     // padded smem row stride (conflict-free: 61 odd)

// Scratch (device globals; no allocation allowed). Zero-initialized at load.
__device__ float g_partial[NBLK][128];  // [b][0:60)=lhs1 (t*5+f), [60:120)=M (f*12+t')
__device__ float g_At2[144];            // At2[t'][t] row-major
__device__ unsigned int g_ticket;       // self-resetting
__device__ unsigned int g_flag;         // self-resetting
__device__ unsigned int g_done;         // self-resetting

// ---------------------------------------------------------------------------
// Per-half conv stage: outputs t = 6h..6h+5 for node (n0+nl), x2 window
// covers t = tlo..tlo+6 with 1-t halo.
// ---------------------------------------------------------------------------
template <int H>
__device__ __forceinline__ void node_half(
    const float* __restrict__ xrow,   // smem: xs + nl*XROW
    const float* __restrict__ sA, const float* __restrict__ sw,
    const float* __restrict__ sb, int n, float* __restrict__ out)
{
    const int tlo = H ? 5 : 0;
    float x2[5][7];
#pragma unroll
    for (int f = 0; f < 5; f++)
#pragma unroll
        for (int k = 0; k < 7; k++) x2[f][k] = 0.f;

#pragma unroll
    for (int tp = 0; tp < 12; tp++) {
        float a[7];
#pragma unroll
        for (int k = 0; k < 7; k++) a[k] = sA[tp * 12 + tlo + k];
#pragma unroll
        for (int f = 0; f < 5; f++) {
            float xv = xrow[tp * 5 + f];
#pragma unroll
            for (int k = 0; k < 7; k++) x2[f][k] += xv * a[k];
        }
    }

#pragma unroll
    for (int o = 0; o < 5; o++) {
        float wr[15];
#pragma unroll
        for (int q = 0; q < 15; q++) wr[q] = sw[o * 15 + q];
        float y[6];
#pragma unroll
        for (int u = 0; u < 6; u++) {
            const int t = 6 * H + u;
            const int k = t - tlo;
            float acc = sb[o];
#pragma unroll
            for (int i = 0; i < 5; i++) {
                if (t > 0)  acc += wr[i * 3 + 0] * x2[i][k - 1];
                acc += wr[i * 3 + 1] * x2[i][k];
                if (t < 11) acc += wr[i * 3 + 2] * x2[i][k + 1];
            }
            y[u] = acc;
        }
        float2* op = (float2*)(out + (size_t)o * NNODE * TDIM
                                   + (size_t)n * TDIM + 6 * H);
        op[0] = make_float2(y[0], y[1]);
        op[1] = make_float2(y[2], y[3]);
        op[2] = make_float2(y[4], y[5]);
    }
}

// ---------------------------------------------------------------------------
// Fully fused kernel: partial reductions -> (tail block) attention ->
// flag release -> conv stage on the smem-resident x tile.
// ---------------------------------------------------------------------------
__global__ void __launch_bounds__(128) k_fused(
    const float* __restrict__ x, const float* __restrict__ U1,
    const float* __restrict__ U2, const float* __restrict__ U3,
    const float* __restrict__ be, const float* __restrict__ Ve,
    const float* __restrict__ w2, const float* __restrict__ b2,
    float* __restrict__ out)
{
    __shared__ float xs[NPB * XROW];      // x[n][j], padded stride
    __shared__ float rhss[NPB * 12];      // rhs[n][t']
    __shared__ float u1s[NPB];
    __shared__ float u2s[5 * NPB];
    __shared__ float sw[75], sb[5], sA[144];
    __shared__ float lhs[60], Mm[60], S[144], E[144];
    __shared__ unsigned int s_t;

    const int tid = threadIdx.x;
    const int blk = blockIdx.x;
    const int n0 = blk * NPB;

    // ---- load tile (coalesced) + params ----
    const float* gx = x + (size_t)n0 * 60;
    for (int i = tid; i < NPB * 60; i += 128)
        xs[(i / 60) * XROW + (i % 60)] = gx[i];
    if (tid < NPB) u1s[tid] = U1[n0 + tid];
    for (int i = tid; i < 5 * NPB; i += 128)
        u2s[i] = U2[(i / NPB) * NNODE + n0 + (i % NPB)];
    if (tid < 75) sw[tid] = w2[tid];
    if (tid < 5)  sb[tid] = b2[tid];
    __syncthreads();

    // ---- rhs[n][t'] = sum_g U3[g]*x[n,t',g] ----
    if (tid < NPB) {
        float u3[5];
#pragma unroll
        for (int f = 0; f < 5; f++) u3[f] = U3[f];
        const float* xr = xs + tid * XROW;
#pragma unroll
        for (int t = 0; t < 12; t++) {
            float s = 0.f;
#pragma unroll
            for (int f = 0; f < 5; f++) s += u3[f] * xr[t * 5 + f];
            rhss[tid * 12 + t] = s;
        }
    }
    __syncthreads();

    // ---- per-component partial sums over this block's 64 nodes ----
    if (tid < 120) {
        float s = 0.f;
        if (tid < 60) {
#pragma unroll 8
            for (int n = 0; n < NPB; n++) s += u1s[n] * xs[n * XROW + tid];
        } else {
            const int f = (tid - 60) / 12, t = (tid - 60) % 12;
#pragma unroll 8
            for (int n = 0; n < NPB; n++) s += u2s[f * NPB + n] * rhss[n * 12 + t];
        }
        g_partial[blk][tid] = s;
    }
    __threadfence();
    if (tid == 0) s_t = atomicAdd(&g_ticket, 1u);
    __syncthreads();

    if (s_t == (unsigned)(NBLK - 1)) {
        // ---- tail block: finish reduction + attention ----
        if (tid < 120) {
            float s = 0.f;
#pragma unroll 5
            for (int b = 0; b < NBLK; b++) s += g_partial[b][tid];
            if (tid < 60) lhs[tid] = s;
            else          Mm[tid - 60] = s;
        }
        __syncthreads();
        for (int j = tid; j < 144; j += 128) {
            const int i = j / 12, c = j % 12;
            float p = 0.f;
#pragma unroll
            for (int f = 0; f < 5; f++) p += lhs[i * 5 + f] * Mm[f * 12 + c];
            p += be[j];
            S[j] = 1.f / (1.f + expf(-p));
        }
        __syncthreads();
        for (int j = tid; j < 144; j += 128) {
            const int i = j / 12, c = j % 12;
            float e = 0.f;
#pragma unroll
            for (int k = 0; k < 12; k++) e += Ve[i * 12 + k] * S[k * 12 + c];
            E[j] = e;
        }
        __syncthreads();
        for (int j = tid; j < 144; j += 128) {
            const int c = j % 12;
            float mx = -1e30f;
#pragma unroll
            for (int k = 0; k < 12; k++) mx = fmaxf(mx, E[k * 12 + c]);
            float sum = 0.f;
#pragma unroll
            for (int k = 0; k < 12; k++) sum += expf(E[k * 12 + c] - mx);
            g_At2[j] = expf(E[j] - mx) / sum;
        }
        __threadfence();          // publish g_At2 (each writer fences)
        __syncthreads();
        if (tid == 0) atomicExch(&g_flag, 1u);   // release
    } else {
        // ---- wait for attention matrix ----
        if (tid == 0) {
            while (atomicAdd(&g_flag, 0u) == 0u) __nanosleep(40);
        }
        __syncthreads();
        __threadfence();          // acquire + compiler barrier
    }

    // ---- stage At2 to smem (L2-fresh reads) ----
    for (int j = tid; j < 144; j += 128) sA[j] = __ldcg(&g_At2[j]);
    __syncthreads();

    // ---- conv stage on smem-resident x tile: 2 threads per node ----
    {
        const int nl = tid >> 1;          // local node 0..63
        const int n  = n0 + nl;
        const float* xrow = xs + nl * XROW;
        if (tid & 1) node_half<1>(xrow, sA, sw, sb, n, out);
        else         node_half<0>(xrow, sA, sw, sb, n, out);
    }

    // ---- reset counters for next graph replay ----
    if (tid == 0) {
        unsigned int d = atomicAdd(&g_done, 1u);
        if (d == (unsigned)(NBLK - 1)) {
            g_ticket = 0u;
            g_flag = 0u;
            g_done = 0u;
            __threadfence();
        }
    }
}

extern "C" void kernel_launch(void* const* d_in, const int* in_sizes, int n_in,
                              void* d_out, int out_size)
{
    // metadata order: x, adj, U1_1, U2_1, U3_1, be_1, Ve_1,
    //                 U1_2, U2_2, U3_2, be_2, Ve_2,
    //                 conv1_w, conv1_b, conv2_w, conv2_b, W_hgc, b_hgc
    const float* x  = (const float*)d_in[0];
    const float* U1 = (const float*)d_in[7];
    const float* U2 = (const float*)d_in[8];
    const float* U3 = (const float*)d_in[9];
    const float* be = (const float*)d_in[10];
    const float* Ve = (const float*)d_in[11];
    const float* w2 = (const float*)d_in[14];
    const float* b2 = (const float*)d_in[15];
    float* out = (float*)d_out;

    k_fused<<<NBLK, 128>>>(x, U1, U2, U3, be, Ve, w2, b2, out);
}

// round 6
// speedup vs baseline: 1.3685x; 1.2439x over previous
#include <cuda_runtime.h>

#define NNODE 8000
#define TDIM 12
#define NBLK1 80
#define NPB1 100      // 80*100 = 8000
#define NBLK2 125
#define NPB2 64       // 125*64 = 8000
#define XROW 61       // padded smem row stride

// Scratch (device globals; no allocation allowed). Zero-initialized at load.
__device__ float g_partial[NBLK1][120];
__device__ float g_At2[144];            // At2[t'][t] row-major
__device__ unsigned int g_ticket;       // self-resetting

// ===========================================================================
// K1: block-local partial reductions through smem; ticket-elected tail block
// finishes the 80-way reduction and computes
//   At2 = softmax_col( Ve @ sigmoid(lhs1 @ M + be) )
// where lhs1[t,f] = sum_n U1[n]*x[n,t,f],
//       M[f,t']   = sum_n U2[f,n]*(sum_g U3[g]*x[n,t',g]).
// ===========================================================================
__global__ void __launch_bounds__(256) k_reduce_att(
    const float* __restrict__ x, const float* __restrict__ U1,
    const float* __restrict__ U2, const float* __restrict__ U3,
    const float* __restrict__ be, const float* __restrict__ Ve)
{
    __shared__ float xs[NPB1 * XROW];
    __shared__ float rhss[NPB1 * 12];
    __shared__ float u1s[NPB1];
    __shared__ float u2s[5 * NPB1];
    __shared__ float sred[240];
    __shared__ unsigned int s_t;

    const int tid = threadIdx.x;
    const int blk = blockIdx.x;
    const int n0 = blk * NPB1;

    // ---- coalesced tile load: 100 nodes x 60 feats (each float4 in-row) ----
    const float4* gx4 = (const float4*)(x + (size_t)n0 * 60);
#pragma unroll
    for (int q = tid; q < NPB1 * 15; q += 256) {
        float4 v = gx4[q];
        const int e = q * 4;
        float* d = &xs[(e / 60) * XROW + (e % 60)];
        d[0] = v.x; d[1] = v.y; d[2] = v.z; d[3] = v.w;
    }
    if (tid < NPB1) u1s[tid] = U1[n0 + tid];
    for (int i = tid; i < 5 * NPB1; i += 256)
        u2s[i] = U2[(i / NPB1) * NNODE + n0 + (i % NPB1)];
    float u3[5];
#pragma unroll
    for (int f = 0; f < 5; f++) u3[f] = U3[f];
    __syncthreads();

    // ---- rhs[n][t'] = sum_g U3[g]*x[n,t',g] ----
    if (tid < NPB1) {
        const float* xr = &xs[tid * XROW];
#pragma unroll
        for (int t = 0; t < 12; t++) {
            float s = 0.f;
#pragma unroll
            for (int f = 0; f < 5; f++) s += u3[f] * xr[t * 5 + f];
            rhss[tid * 12 + t] = s;
        }
    }
    __syncthreads();

    // ---- per-component partials: 2 threads/component over 50-node halves ----
    if (tid < 240) {
        const int c = tid % 120, h = tid / 120;
        const int nlo = h * 50;
        float s = 0.f;
        if (c < 60) {
#pragma unroll 10
            for (int n = nlo; n < nlo + 50; n++) s += u1s[n] * xs[n * XROW + c];
        } else {
            const int f = (c - 60) / 12, t = (c - 60) % 12;
#pragma unroll 10
            for (int n = nlo; n < nlo + 50; n++) s += u2s[f * NPB1 + n] * rhss[n * 12 + t];
        }
        sred[tid] = s;
    }
    __syncthreads();
    if (tid < 120) g_partial[blk][tid] = sred[tid] + sred[tid + 120];
    __threadfence();
    if (tid == 0) s_t = atomicAdd(&g_ticket, 1u);
    __syncthreads();
    if (s_t != (unsigned)(NBLK1 - 1)) return;

    // ---- tail block: finish reduction (2 threads/component, 40 blocks each) ----
    __threadfence();  // acquire: partials of all other blocks
    if (tid < 240) {
        const int c = tid % 120, h = tid / 120;
        float s = 0.f;
#pragma unroll 8
        for (int b = h * 40; b < h * 40 + 40; b++) s += g_partial[b][c];
        sred[tid] = s;
    }
    __syncthreads();
    __shared__ float lhs[60], Mm[60], S[144], E[144];
    if (tid < 120) {
        const float s = sred[tid] + sred[tid + 120];
        if (tid < 60) lhs[tid] = s;
        else          Mm[tid - 60] = s;
    }
    __syncthreads();
    if (tid < 144) {
        const int i = tid / 12, c = tid % 12;
        float p = 0.f;
#pragma unroll
        for (int f = 0; f < 5; f++) p += lhs[i * 5 + f] * Mm[f * 12 + c];
        p += be[tid];
        S[tid] = 1.f / (1.f + expf(-p));
    }
    __syncthreads();
    if (tid < 144) {
        const int i = tid / 12, c = tid % 12;
        float e = 0.f;
#pragma unroll
        for (int k = 0; k < 12; k++) e += Ve[i * 12 + k] * S[k * 12 + c];
        E[tid] = e;
    }
    __syncthreads();
    if (tid < 144) {
        const int c = tid % 12;
        float mx = -1e30f;
#pragma unroll
        for (int k = 0; k < 12; k++) mx = fmaxf(mx, E[k * 12 + c]);
        float sum = 0.f;
#pragma unroll
        for (int k = 0; k < 12; k++) sum += expf(E[k * 12 + c] - mx);
        g_At2[tid] = expf(E[tid] - mx) / sum;
    }
    if (tid == 0) { g_ticket = 0u; __threadfence(); }  // reset for replay
}

// ===========================================================================
// K2: conv stage. 64 nodes/block in smem, 4 threads/node (t-quarters).
//   x2[f][t] = sum_{t'} x[n,t',f] * At2[t'][t]
//   y[o][t]  = b2[o] + sum_i sum_k w2[o,i,k]*x2[i][t+k-1]
// Output (o, n, t) row-major == flat output buffer.
// ===========================================================================
template <int H>
__device__ __forceinline__ void node_quarter(
    const float* __restrict__ xrow, const float* __restrict__ sA,
    const float* __restrict__ sw, const float* __restrict__ sb,
    int n, float* __restrict__ out)
{
    constexpr int TLO = (H == 0) ? 0 : (3 * H - 1);
    constexpr int THI = (H == 3) ? 11 : (3 * H + 3);
    constexpr int W = THI - TLO + 1;   // 4,5,5,4

    float x2[5][W];
#pragma unroll
    for (int f = 0; f < 5; f++)
#pragma unroll
        for (int k = 0; k < W; k++) x2[f][k] = 0.f;

#pragma unroll
    for (int tp = 0; tp < 12; tp++) {
        float a[W];
#pragma unroll
        for (int k = 0; k < W; k++) a[k] = sA[tp * 12 + TLO + k];
#pragma unroll
        for (int f = 0; f < 5; f++) {
            const float xv = xrow[tp * 5 + f];
#pragma unroll
            for (int k = 0; k < W; k++) x2[f][k] += xv * a[k];
        }
    }

#pragma unroll
    for (int o = 0; o < 5; o++) {
        float wr[15];
#pragma unroll
        for (int q = 0; q < 15; q++) wr[q] = sw[o * 15 + q];
        float* op = out + (size_t)o * NNODE * TDIM + (size_t)n * TDIM + 3 * H;
#pragma unroll
        for (int u = 0; u < 3; u++) {
            const int t = 3 * H + u;
            const int k = t - TLO;
            float acc = sb[o];
#pragma unroll
            for (int i = 0; i < 5; i++) {
                if (t > 0)  acc += wr[i * 3 + 0] * x2[i][k - 1];
                acc += wr[i * 3 + 1] * x2[i][k];
                if (t < 11) acc += wr[i * 3 + 2] * x2[i][k + 1];
            }
            op[u] = acc;
        }
    }
}

__global__ void __launch_bounds__(256) k_conv(
    const float* __restrict__ x, const float* __restrict__ w2,
    const float* __restrict__ b2, float* __restrict__ out)
{
    __shared__ float xs[NPB2 * XROW];
    __shared__ float sA[144], sw[75], sb[5];

    const int tid = threadIdx.x;
    const int n0 = blockIdx.x * NPB2;

    const float4* gx4 = (const float4*)(x + (size_t)n0 * 60);
#pragma unroll
    for (int q = tid; q < NPB2 * 15; q += 256) {
        float4 v = gx4[q];
        const int e = q * 4;
        float* d = &xs[(e / 60) * XROW + (e % 60)];
        d[0] = v.x; d[1] = v.y; d[2] = v.z; d[3] = v.w;
    }
    if (tid < 144) sA[tid] = g_At2[tid];
    if (tid < 75)  sw[tid] = w2[tid];
    if (tid < 5)   sb[tid] = b2[tid];
    __syncthreads();

    const int nl = tid >> 2;
    const int h = tid & 3;
    const int n = n0 + nl;
    const float* xrow = &xs[nl * XROW];

    switch (h) {
        case 0: node_quarter<0>(xrow, sA, sw, sb, n, out); break;
        case 1: node_quarter<1>(xrow, sA, sw, sb, n, out); break;
        case 2: node_quarter<2>(xrow, sA, sw, sb, n, out); break;
        default: node_quarter<3>(xrow, sA, sw, sb, n, out); break;
    }
}

extern "C" void kernel_launch(void* const* d_in, const int* in_sizes, int n_in,
                              void* d_out, int out_size)
{
    // metadata order: x, adj, U1_1, U2_1, U3_1, be_1, Ve_1,
    //                 U1_2, U2_2, U3_2, be_2, Ve_2,
    //                 conv1_w, conv1_b, conv2_w, conv2_b, W_hgc, b_hgc
    const float* x  = (const float*)d_in[0];
    const float* U1 = (const float*)d_in[7];
    const float* U2 = (const float*)d_in[8];
    const float* U3 = (const float*)d_in[9];
    const float* be = (const float*)d_in[10];
    const float* Ve = (const float*)d_in[11];
    const float* w2 = (const float*)d_in[14];
    const float* b2 = (const float*)d_in[15];
    float* out = (float*)d_out;

    k_reduce_att<<<NBLK1, 256>>>(x, U1, U2, U3, be, Ve);
    k_conv<<<NBLK2, 256>>>(x, w2, b2, out);
}

// round 7
// speedup vs baseline: 1.5009x; 1.0968x over previous
#include <cuda_runtime.h>

#define NNODE 8000
#define TDIM 12
#define NBLK1 80
#define NPB1 100      // 80*100 = 8000
#define NBLK2 125
#define NPB2 64       // 125*64 = 8000
#define XROW 61       // padded smem row stride (odd => conflict-free column reads)
#define RPAD 104      // rhss row stride (even, 8B-aligned pairs)

typedef unsigned long long u64t;

// Scratch (device globals; no allocation allowed). Zero-initialized at load.
__device__ float g_partial[NBLK1][120];
__device__ float g_At2[144];            // At2[t'][t] row-major
__device__ unsigned int g_ticket;       // self-resetting

// ---- f32x2 packed math helpers (sm_103a; PTX-only, ptxas won't auto-fuse) ----
__device__ __forceinline__ u64t pack2(float lo, float hi) {
    u64t d; asm("mov.b64 %0,{%1,%2};" : "=l"(d) : "f"(lo), "f"(hi)); return d;
}
__device__ __forceinline__ u64t fma2(u64t a, u64t b, u64t c) {
    u64t d; asm("fma.rn.f32x2 %0,%1,%2,%3;" : "=l"(d) : "l"(a), "l"(b), "l"(c));
    return d;
}
__device__ __forceinline__ void unpack2(u64t v, float& lo, float& hi) {
    asm("mov.b64 {%0,%1},%2;" : "=f"(lo), "=f"(hi) : "l"(v));
}

// ===========================================================================
// K1: block-local partial reductions through smem; ticket-elected tail block
// finishes the 80-way reduction and computes
//   At2 = softmax_col( Ve @ sigmoid(lhs1 @ M + be) )
//   lhs1[t,f] = sum_n U1[n]*x[n,t,f]
//   M[f,t']   = sum_n U2[f,n]*(sum_g U3[g]*x[n,t',g])
// ===========================================================================
__global__ void __launch_bounds__(256) k_reduce_att(
    const float* __restrict__ x, const float* __restrict__ U1,
    const float* __restrict__ U2, const float* __restrict__ U3,
    const float* __restrict__ be, const float* __restrict__ Ve)
{
    cudaTriggerProgrammaticLaunchCompletion();  // let K2 start its prologue now

    __shared__ float xs[NPB1 * XROW];
    __shared__ __align__(8) float rhss[12 * RPAD];   // [t'][n]
    __shared__ __align__(8) float u1s[NPB1];
    __shared__ __align__(8) float u2s[5 * NPB1];     // [f][n]
    __shared__ float sred[240];
    __shared__ unsigned int s_t;

    const int tid = threadIdx.x;
    const int blk = blockIdx.x;
    const int n0 = blk * NPB1;

    // ---- coalesced tile load: 100 nodes x 60 feats ----
    const float4* gx4 = (const float4*)(x + (size_t)n0 * 60);
#pragma unroll
    for (int q = tid; q < NPB1 * 15; q += 256) {
        float4 v = gx4[q];
        const int e = q * 4;
        float* d = &xs[(e / 60) * XROW + (e % 60)];
        d[0] = v.x; d[1] = v.y; d[2] = v.z; d[3] = v.w;
    }
    if (tid < NPB1) u1s[tid] = U1[n0 + tid];
    for (int i = tid; i < 5 * NPB1; i += 256)
        u2s[i] = U2[(i / NPB1) * NNODE + n0 + (i % NPB1)];
    float u3[5];
#pragma unroll
    for (int f = 0; f < 5; f++) u3[f] = U3[f];
    __syncthreads();

    // ---- rhs[t'][n] = sum_g U3[g]*x[n,t',g] ----
    if (tid < NPB1) {
        const float* xr = &xs[tid * XROW];
#pragma unroll
        for (int t = 0; t < 12; t++) {
            float s = 0.f;
#pragma unroll
            for (int f = 0; f < 5; f++) s += u3[f] * xr[t * 5 + f];
            rhss[t * RPAD + tid] = s;
        }
    }
    __syncthreads();

    // ---- per-component partials: 2 threads/component over 50-node halves ----
    if (tid < 240) {
        const int c = tid % 120, h = tid / 120;
        const int nlo = h * 50;
        float s;
        if (c < 60) {
            s = 0.f;
#pragma unroll 10
            for (int n = nlo; n < nlo + 50; n++) s += u1s[n] * xs[n * XROW + c];
        } else {
            const int f = (c - 60) / 12, t = (c - 60) % 12;
            const u64t* up = (const u64t*)(u2s + f * NPB1 + nlo);
            const u64t* rp = (const u64t*)(rhss + t * RPAD + nlo);
            u64t acc = 0ull;
#pragma unroll
            for (int j = 0; j < 25; j++) acc = fma2(up[j], rp[j], acc);
            float lo, hi; unpack2(acc, lo, hi);
            s = lo + hi;
        }
        sred[tid] = s;
    }
    __syncthreads();
    if (tid < 120) g_partial[blk][tid] = sred[tid] + sred[tid + 120];
    __threadfence();
    if (tid == 0) s_t = atomicAdd(&g_ticket, 1u);
    __syncthreads();
    if (s_t != (unsigned)(NBLK1 - 1)) return;

    // ---- tail block: finish reduction (2 threads/component, 40 blocks each) ----
    __threadfence();  // acquire
    if (tid < 240) {
        const int c = tid % 120, h = tid / 120;
        float s = 0.f;
#pragma unroll 8
        for (int b = h * 40; b < h * 40 + 40; b++) s += g_partial[b][c];
        sred[tid] = s;
    }
    __syncthreads();
    __shared__ float lhs[60], Mm[60], S[144], E[144];
    if (tid < 120) {
        const float s = sred[tid] + sred[tid + 120];
        if (tid < 60) lhs[tid] = s;
        else          Mm[tid - 60] = s;
    }
    __syncthreads();
    if (tid < 144) {
        const int i = tid / 12, c = tid % 12;
        float p = 0.f;
#pragma unroll
        for (int f = 0; f < 5; f++) p += lhs[i * 5 + f] * Mm[f * 12 + c];
        p += be[tid];
        S[tid] = 1.f / (1.f + expf(-p));
    }
    __syncthreads();
    if (tid < 144) {
        const int i = tid / 12, c = tid % 12;
        float e = 0.f;
#pragma unroll
        for (int k = 0; k < 12; k++) e += Ve[i * 12 + k] * S[k * 12 + c];
        E[tid] = e;
    }
    __syncthreads();
    if (tid < 144) {
        const int c = tid % 12;
        float mx = -1e30f;
#pragma unroll
        for (int k = 0; k < 12; k++) mx = fmaxf(mx, E[k * 12 + c]);
        float sum = 0.f;
#pragma unroll
        for (int k = 0; k < 12; k++) sum += expf(E[k * 12 + c] - mx);
        g_At2[tid] = expf(E[tid] - mx) / sum;
    }
    if (tid == 0) { g_ticket = 0u; __threadfence(); }  // reset for replay
}

// ===========================================================================
// K2: conv stage. 64 nodes/block in smem, 4 threads/node (t-quarters).
// t-windows start at even offsets so At2 rows load as LDS.64 and the x2
// accumulation runs on packed f32x2 FMAs.
//   x2[f][t] = sum_{t'} x[n,t',f] * At2[t'][t]
//   y[o][t]  = b2[o] + sum_i sum_k w2[o,i,k]*x2[i][t+k-1]
// ===========================================================================
template <int H>
__device__ __forceinline__ void node_quarter(
    const float* __restrict__ xrow, const float* __restrict__ sA,
    const float* __restrict__ sw, const float* __restrict__ sb,
    int n, float* __restrict__ out)
{
    constexpr int TLO = (H == 0) ? 0 : (H == 1) ? 2 : (H == 2) ? 4 : 8;
    constexpr int W   = (H == 0 || H == 3) ? 4 : 6;
    constexpr int P   = W / 2;

    u64t x2p[5][P];
#pragma unroll
    for (int f = 0; f < 5; f++)
#pragma unroll
        for (int j = 0; j < P; j++) x2p[f][j] = 0ull;

#pragma unroll
    for (int tp = 0; tp < 12; tp++) {
        u64t a2[P];
        const u64t* ap = (const u64t*)(sA + tp * 12 + TLO);
#pragma unroll
        for (int j = 0; j < P; j++) a2[j] = ap[j];
#pragma unroll
        for (int f = 0; f < 5; f++) {
            const float xv = xrow[tp * 5 + f];
            const u64t xvv = pack2(xv, xv);
#pragma unroll
            for (int j = 0; j < P; j++) x2p[f][j] = fma2(xvv, a2[j], x2p[f][j]);
        }
    }

    float x2[5][W];
#pragma unroll
    for (int f = 0; f < 5; f++)
#pragma unroll
        for (int j = 0; j < P; j++) unpack2(x2p[f][j], x2[f][2 * j], x2[f][2 * j + 1]);

#pragma unroll
    for (int o = 0; o < 5; o++) {
        float wr[15];
#pragma unroll
        for (int q = 0; q < 15; q++) wr[q] = sw[o * 15 + q];
        float* op = out + (size_t)o * NNODE * TDIM + (size_t)n * TDIM + 3 * H;
#pragma unroll
        for (int u = 0; u < 3; u++) {
            const int t = 3 * H + u;
            const int k = t - TLO;
            float acc = sb[o];
#pragma unroll
            for (int i = 0; i < 5; i++) {
                if (t > 0)  acc += wr[i * 3 + 0] * x2[i][k - 1];
                acc += wr[i * 3 + 1] * x2[i][k];
                if (t < 11) acc += wr[i * 3 + 2] * x2[i][k + 1];
            }
            op[u] = acc;
        }
    }
}

__global__ void __launch_bounds__(256) k_conv(
    const float* __restrict__ x, const float* __restrict__ w2,
    const float* __restrict__ b2, float* __restrict__ out)
{
    __shared__ float xs[NPB2 * XROW];
    __shared__ __align__(16) float sA[144];
    __shared__ float sw[75], sb[5];

    const int tid = threadIdx.x;
    const int n0 = blockIdx.x * NPB2;

    // ---- prologue: runs concurrently with K1 under PDL ----
    const float4* gx4 = (const float4*)(x + (size_t)n0 * 60);
#pragma unroll
    for (int q = tid; q < NPB2 * 15; q += 256) {
        float4 v = gx4[q];
        const int e = q * 4;
        float* d = &xs[(e / 60) * XROW + (e % 60)];
        d[0] = v.x; d[1] = v.y; d[2] = v.z; d[3] = v.w;
    }
    if (tid < 75) sw[tid] = w2[tid];
    if (tid < 5)  sb[tid] = b2[tid];

    // ---- wait for K1 grid completion (g_At2 visible), then stage it ----
    cudaGridDependencySynchronize();
    if (tid < 144) sA[tid] = g_At2[tid];
    __syncthreads();

    const int nl = tid >> 2;
    const int h = tid & 3;
    const int n = n0 + nl;
    const float* xrow = &xs[nl * XROW];

    switch (h) {
        case 0: node_quarter<0>(xrow, sA, sw, sb, n, out); break;
        case 1: node_quarter<1>(xrow, sA, sw, sb, n, out); break;
        case 2: node_quarter<2>(xrow, sA, sw, sb, n, out); break;
        default: node_quarter<3>(xrow, sA, sw, sb, n, out); break;
    }
}

extern "C" void kernel_launch(void* const* d_in, const int* in_sizes, int n_in,
                              void* d_out, int out_size)
{
    // metadata order: x, adj, U1_1, U2_1, U3_1, be_1, Ve_1,
    //                 U1_2, U2_2, U3_2, be_2, Ve_2,
    //                 conv1_w, conv1_b, conv2_w, conv2_b, W_hgc, b_hgc
    const float* x  = (const float*)d_in[0];
    const float* U1 = (const float*)d_in[7];
    const float* U2 = (const float*)d_in[8];
    const float* U3 = (const float*)d_in[9];
    const float* be = (const float*)d_in[10];
    const float* Ve = (const float*)d_in[11];
    const float* w2 = (const float*)d_in[14];
    const float* b2 = (const float*)d_in[15];
    float* out = (float*)d_out;

    k_reduce_att<<<NBLK1, 256>>>(x, U1, U2, U3, be, Ve);

    cudaLaunchConfig_t cfg = {};
    cfg.gridDim = dim3(NBLK2);
    cfg.blockDim = dim3(256);
    cfg.dynamicSmemBytes = 0;
    cudaLaunchAttribute attr[1];
    attr[0].id = cudaLaunchAttributeProgrammaticStreamSerialization;
    attr[0].val.programmaticStreamSerializationAllowed = 1;
    cfg.attrs = attr;
    cfg.numAttrs = 1;
    cudaLaunchKernelEx(&cfg, k_conv, x, w2, b2, out);
}